// round 13
// baseline (speedup 1.0000x reference)
#include <cuda_runtime.h>
#include <cuda_bf16.h>

#define NN 4096
#define BB 2
#define CC 64
#define MSPLIT 4

typedef unsigned int u32;

// Scratch
__device__ __nv_bfloat16 g_qh[(size_t)BB * NN * 8];           // [b][n][8c] (q pre-scaled by log2e)
__device__ __nv_bfloat16 g_kh[(size_t)BB * NN * 8];           // [b][m][8c]
__device__ __nv_bfloat16 g_vh[(size_t)BB * CC * NN];          // [b][c][m]
__device__ __nv_bfloat16 g_po[(size_t)MSPLIT * BB * CC * NN]; // partial O [s][b][c][n]
__device__ float g_prs[(size_t)MSPLIT * BB * NN];             // partial rowsum [s][b][n]
__device__ int g_tk[BB * 64];                                 // tickets (mod-MSPLIT)

// Per-group stage: K slice 512B (32 rows x 16B) + V slice (64 c-rows x 80B, 64B data)
#define STG_K 512
#define STG_SZ 5632            // 512 + 64*80
#define GRP_SZ (4 * STG_SZ)    // 4-stage ring per group

__device__ __forceinline__ u32 packbf(float lo, float hi) {
    u32 r;
    asm("cvt.rn.bf16x2.f32 %0, %1, %2;" : "=r"(r) : "f"(hi), "f"(lo));
    return r;
}
__device__ __forceinline__ float2 unpackbf(u32 v) {
    __nv_bfloat162 h = *(__nv_bfloat162*)&v;
    return make_float2(__bfloat162float(h.x), __bfloat162float(h.y));
}
__device__ __forceinline__ float ex2(float x) {
    float y;
    asm("ex2.approx.ftz.f32 %0, %1;" : "=f"(y) : "f"(x));
    return y;
}

__device__ __forceinline__ void mma_bf16_k8(float d[4], u32 a0, u32 a1, u32 b0) {
    asm("mma.sync.aligned.m16n8k8.row.col.f32.bf16.bf16.f32 "
        "{%0,%1,%2,%3}, {%4,%5}, {%6}, {%0,%1,%2,%3};"
        : "+f"(d[0]), "+f"(d[1]), "+f"(d[2]), "+f"(d[3])
        : "r"(a0), "r"(a1), "r"(b0));
}
__device__ __forceinline__ void mma_bf16_k16(float d[4], u32 a0, u32 a1, u32 a2, u32 a3,
                                             u32 b0, u32 b1) {
    asm("mma.sync.aligned.m16n8k16.row.col.f32.bf16.bf16.f32 "
        "{%0,%1,%2,%3}, {%4,%5,%6,%7}, {%8,%9}, {%0,%1,%2,%3};"
        : "+f"(d[0]), "+f"(d[1]), "+f"(d[2]), "+f"(d[3])
        : "r"(a0), "r"(a1), "r"(a2), "r"(a3), "r"(b0), "r"(b1));
}
__device__ __forceinline__ void ldsm_x4(u32& r0, u32& r1, u32& r2, u32& r3, u32 saddr) {
    asm volatile("ldmatrix.sync.aligned.m8n8.x4.shared.b16 {%0,%1,%2,%3}, [%4];"
                 : "=r"(r0), "=r"(r1), "=r"(r2), "=r"(r3) : "r"(saddr));
}
__device__ __forceinline__ void cp16(u32 dst, const void* src) {
    asm volatile("cp.async.cg.shared.global [%0], [%1], 16;" :: "r"(dst), "l"(src));
}
__device__ __forceinline__ void cp4(u32 dst, const void* src) {
    asm volatile("cp.async.ca.shared.global [%0], [%1], 4;" :: "r"(dst), "l"(src));
}
__device__ __forceinline__ void cp_commit() { asm volatile("cp.async.commit_group;"); }
__device__ __forceinline__ void cp_wait0() { asm volatile("cp.async.wait_group 0;"); }
__device__ __forceinline__ void cp_wait2() { asm volatile("cp.async.wait_group 2;"); }
__device__ __forceinline__ void gbar(int id) {
    asm volatile("bar.sync %0, 128;" :: "r"(id) : "memory");
}

// ---------------------------------------------------------------------------
// Fused projection kernel, ONE launch, 512 CTAs. (unchanged)
// ---------------------------------------------------------------------------
__global__ __launch_bounds__(256) void proj_kernel(const float* __restrict__ x,
                                                   const float* __restrict__ ctx,
                                                   const float* __restrict__ Wq,
                                                   const float* __restrict__ bq,
                                                   const float* __restrict__ Wk,
                                                   const float* __restrict__ bk,
                                                   const float* __restrict__ Wv,
                                                   const float* __restrict__ bv) {
    const int tid = threadIdx.x;
    const int role = blockIdx.x >> 8;
    const int idx = blockIdx.x & 255;
    const int b = idx >> 7;
    const int n0 = (idx & 127) * 32;
    const float LOG2E = 1.4426950408889634f;

    if (role == 0) {
        __shared__ float sx[64][36];
        __shared__ float sct[64][36];
        __shared__ float sW[16][64];
        __shared__ float sb[16];

        for (int i = tid; i < 512; i += 256) {
            sW[i >> 6][i & 63] = Wq[i] * LOG2E;
            sW[8 + (i >> 6)][i & 63] = Wk[i];
        }
        if (tid < 8) { sb[tid] = bq[tid] * LOG2E; sb[8 + tid] = bk[tid]; }
#pragma unroll
        for (int k = 0; k < 2; k++) {
            int i = k * 256 + tid;
            int r = i >> 3, f4 = (i & 7) * 4;
            *(float4*)&sx[r][f4] = *(const float4*)&x[((size_t)b * CC + r) * NN + n0 + f4];
            *(float4*)&sct[r][f4] = *(const float4*)&ctx[((size_t)b * CC + r) * NN + n0 + f4];
        }
        __syncthreads();

        const int n = tid & 31;
        const int og = tid >> 5;
        const bool isk = og >= 4;
        const int r2 = 2 * (og & 3);
        const int wrow = (isk ? 8 : 0) + r2;
        float a0 = sb[wrow], a1 = sb[wrow + 1];
#pragma unroll
        for (int c = 0; c < 64; c++) {
            float v = isk ? sct[c][n] : sx[c][n];
            a0 = fmaf(sW[wrow][c], v, a0);
            a1 = fmaf(sW[wrow + 1][c], v, a1);
        }
        __nv_bfloat16* dst = isk ? g_kh : g_qh;
        *(u32*)(dst + ((size_t)b * NN + n0 + n) * 8 + r2) = packbf(a0, a1);
    } else {
        __shared__ float sC[64][36];
        __shared__ float sWv[64][68];
        __shared__ float sbv[64];

        for (int i = tid; i < 4096; i += 256) sWv[i & 63][i >> 6] = Wv[i];
        if (tid < 64) sbv[tid] = bv[tid];
#pragma unroll
        for (int k = 0; k < 2; k++) {
            int i = k * 256 + tid;
            int r = i >> 3, f4 = (i & 7) * 4;
            *(float4*)&sC[r][f4] = *(const float4*)&ctx[((size_t)b * CC + r) * NN + n0 + f4];
        }
        __syncthreads();

        const int m2 = (tid & 15) * 2;
        const int cg = (tid >> 4) * 4;
        float acc[4][2];
#pragma unroll
        for (int j = 0; j < 4; j++) acc[j][0] = acc[j][1] = sbv[cg + j];
#pragma unroll
        for (int cc = 0; cc < 64; cc++) {
            float2 vm = *(const float2*)&sC[cc][m2];
            float4 wv = *(const float4*)&sWv[cc][cg];
            float ww[4] = {wv.x, wv.y, wv.z, wv.w};
#pragma unroll
            for (int j = 0; j < 4; j++) {
                acc[j][0] = fmaf(ww[j], vm.x, acc[j][0]);
                acc[j][1] = fmaf(ww[j], vm.y, acc[j][1]);
            }
        }
#pragma unroll
        for (int j = 0; j < 4; j++)
            *(u32*)(g_vh + ((size_t)b * CC + cg + j) * NN + n0 + m2) = packbf(acc[j][0], acc[j][1]);
    }
}

// ---------------------------------------------------------------------------
// Attention: MSPLIT=4 (512 CTAs, 16 chunks each) with the spill-free 80-reg
// loop from R12. Per-group rings + named barriers; lean epilogue; mod-4
// ticket combine. grid (64 qtiles, B, 4), 256 threads, 3 CTAs/SM.
// ---------------------------------------------------------------------------
__global__ __launch_bounds__(256, 3) void attn_kernel(const float* __restrict__ x,
                                                      const float* __restrict__ gammap,
                                                      float* __restrict__ out) {
    __shared__ __nv_bfloat16 sQ[64][8];
    __shared__ __align__(16) char svbuf[2 * GRP_SZ];   // 2 group rings / sO alias
    __shared__ float sRS[64][2];
    __shared__ float sInv[64];
    __shared__ int sFlag;
    float (*sO)[65] = (float (*)[65])svbuf;

    const int tid = threadIdx.x;
    const int b = blockIdx.y;
    const int q0 = blockIdx.x * 64;
    const int s = blockIdx.z;
    const int ck0 = s * 16;
    const int lane = tid & 31;
    const int g = lane >> 2;
    const int t = lane & 3;
    const int qT = (tid >> 5) & 3;
    const int h = tid >> 7;
    const int r = 16 * qT + g;
    const int gt = tid & 127;        // group-local thread id

    const char* gk = (const char*)g_kh + (size_t)b * NN * 8 * 2;
    const char* gv = (const char*)g_vh + (size_t)b * CC * NN * 2;

    ((u32*)sQ)[tid] = ((const u32*)((const char*)g_qh + ((size_t)b * NN + q0) * 16))[tid];

    // Group ring base (shared-space)
    const u32 svb = (u32)__cvta_generic_to_shared(svbuf);
    const u32 gb = svb + h * GRP_SZ;
    const u32 kA = gb + lane * 16;                    // K: local m = lane
    const u32 vA = gb + STG_K + lane * 80;            // V: c = lane
    const u32 vB = vA + 32 * 80;                      // V: c = 32 + lane
    const u32 kDst = gb + gt * 4;
    const u32 vDst = gb + STG_K + (gt >> 1) * 80 + (gt & 1) * 32;
    const char* kSrc = gk + (size_t)(32 * h) * 16 + (gt >> 2) * 16 + (gt & 3) * 4;
    const char* vSrc = gv + ((size_t)(gt >> 1) * NN + 32 * h) * 2 + (gt & 1) * 32;

    // Prologue: stage chunks ck0..ck0+2 into stages 0..2 (this group's slices)
#pragma unroll
    for (int p = 0; p < 3; p++) {
        size_t off = (size_t)(ck0 + p) * 64;
        cp4(kDst + p * STG_SZ, kSrc + off * 16);
        cp16(vDst + p * STG_SZ, vSrc + off * 2);
        cp16(vDst + p * STG_SZ + 16, vSrc + off * 2 + 16);
        cp_commit();
    }

    // sQ is read cross-warp/cross-group: full barrier before Q fragment reads.
    __syncthreads();

    const u32 qa0 = *(const u32*)((const char*)sQ + r * 16 + t * 4);
    const u32 qa1 = *(const u32*)((const char*)sQ + (r + 8) * 16 + t * 4);

    float oC[8][4];
#pragma unroll
    for (int i = 0; i < 8; i++)
#pragma unroll
        for (int j = 0; j < 4; j++) oC[i][j] = 0.0f;
    float rs0 = 0.0f, rs1 = 0.0f;

    for (int ck = 0; ck < 16; ck++) {
        const u32 stOff = (u32)(ck & 3) * STG_SZ;

        // This group's chunk ck resident (2 groups slack); group-scope barrier.
        if (ck < 14) cp_wait2(); else cp_wait0();
        gbar(1 + h);

        // Stage chunk ck+3 into stage (ck+3)&3 (consumed at ck-1, bar above)
        if (ck < 13) {
            size_t off = (size_t)(ck0 + ck + 3) * 64;
            const u32 nb = ((ck + 3) & 3) * STG_SZ;
            cp4(kDst + nb, kSrc + off * 16);
            cp16(vDst + nb, vSrc + off * 2);
            cp16(vDst + nb + 16, vSrc + off * 2 + 16);
            cp_commit();
        }

        u32 kb[4];
        ldsm_x4(kb[0], kb[1], kb[2], kb[3], kA + stOff);

        // ---- per-ks: S(2 mmas) -> bl ldsm -> ex2/pack -> 4 O -> bh ldsm -> 4 O
#pragma unroll
        for (int ks = 0; ks < 2; ks++) {
            const u32 base = stOff + 32 * ks;
            float e0[4] = {0.0f, 0.0f, 0.0f, 0.0f};
            float e1[4] = {0.0f, 0.0f, 0.0f, 0.0f};
            mma_bf16_k8(e0, qa0, qa1, kb[2 * ks]);
            mma_bf16_k8(e1, qa0, qa1, kb[2 * ks + 1]);

            u32 bl[4][2];
            ldsm_x4(bl[0][0], bl[1][0], bl[2][0], bl[3][0], vA + base);
            ldsm_x4(bl[0][1], bl[1][1], bl[2][1], bl[3][1], vA + base + 16);

            float p00 = ex2(e0[0]), p01 = ex2(e0[1]);
            float p02 = ex2(e0[2]), p03 = ex2(e0[3]);
            float p10 = ex2(e1[0]), p11 = ex2(e1[1]);
            float p12 = ex2(e1[2]), p13 = ex2(e1[3]);
            rs0 += p00 + p01 + p10 + p11;
            rs1 += p02 + p03 + p12 + p13;
            u32 a0 = packbf(p00, p01);
            u32 a1 = packbf(p02, p03);
            u32 a2 = packbf(p10, p11);
            u32 a3 = packbf(p12, p13);

#pragma unroll
            for (int cT = 0; cT < 4; cT++)
                mma_bf16_k16(oC[cT], a0, a1, a2, a3, bl[cT][0], bl[cT][1]);

            u32 bh[4][2];
            ldsm_x4(bh[0][0], bh[1][0], bh[2][0], bh[3][0], vB + base);
            ldsm_x4(bh[0][1], bh[1][1], bh[2][1], bh[3][1], vB + base + 16);
#pragma unroll
            for (int cT = 0; cT < 4; cT++)
                mma_bf16_k16(oC[4 + cT], a0, a1, a2, a3, bh[cT][0], bh[cT][1]);
        }
    }

    // Rowsums
    rs0 += __shfl_xor_sync(0xffffffffu, rs0, 1);
    rs0 += __shfl_xor_sync(0xffffffffu, rs0, 2);
    rs1 += __shfl_xor_sync(0xffffffffu, rs1, 1);
    rs1 += __shfl_xor_sync(0xffffffffu, rs1, 2);
    if (t == 0) {
        sRS[r][h] = rs0;
        sRS[r + 8][h] = rs1;
    }
    __syncthreads();   // both groups done; rings dead; sO may be written

    // Cross-h O reduce into sO
    if (h == 0) {
#pragma unroll
        for (int cT = 0; cT < 8; cT++) {
            int c = 8 * cT + 2 * t;
            sO[r][c] = oC[cT][0];
            sO[r][c + 1] = oC[cT][1];
            sO[r + 8][c] = oC[cT][2];
            sO[r + 8][c + 1] = oC[cT][3];
        }
    }
    __syncthreads();
    if (h == 1) {
#pragma unroll
        for (int cT = 0; cT < 8; cT++) {
            int c = 8 * cT + 2 * t;
            sO[r][c] += oC[cT][0];
            sO[r][c + 1] += oC[cT][1];
            sO[r + 8][c] += oC[cT][2];
            sO[r + 8][c + 1] += oC[cT][3];
        }
    }
    __syncthreads();

    // Partial rowsum + partial bf16 O [s][b][c][n]
    if (tid < 64)
        g_prs[((size_t)s * BB + b) * NN + q0 + tid] = sRS[tid][0] + sRS[tid][1];
    {
        u32* po = (u32*)g_po + ((size_t)s * BB + b) * (CC * NN / 2);
#pragma unroll
        for (int k = 0; k < 8; k++) {
            int i = k * 256 + tid;
            int c = i >> 5, n2 = i & 31;
            po[(size_t)c * (NN / 2) + q0 / 2 + n2] = packbf(sO[2 * n2][c], sO[2 * n2 + 1][c]);
        }
    }

    // Ticket: last CTA of this (tile, b) performs the combine
    __threadfence();
    __syncthreads();
    if (tid == 0) sFlag = ((atomicAdd(&g_tk[b * 64 + blockIdx.x], 1) & (MSPLIT - 1)) == MSPLIT - 1);
    __syncthreads();

    if (sFlag) {
        __threadfence();
        if (tid < 64) {
            float rsum = 0.0f;
#pragma unroll
            for (int ss = 0; ss < MSPLIT; ss++)
                rsum += g_prs[((size_t)ss * BB + b) * NN + q0 + tid];
            sInv[tid] = gammap[0] / rsum;
        }
        __syncthreads();
#pragma unroll
        for (int k = 0; k < 8; k++) {
            int i = k * 256 + tid;
            int c = i >> 5, n2 = i & 31;
            size_t pi = (size_t)c * (NN / 2) + q0 / 2 + n2;
            float vx = 0.0f, vy = 0.0f;
#pragma unroll
            for (int ss = 0; ss < MSPLIT; ss++) {
                float2 v = unpackbf(((const u32*)g_po + ((size_t)ss * BB + b) * (CC * NN / 2))[pi]);
                vx += v.x;
                vy += v.y;
            }
            size_t gi = ((size_t)b * CC + c) * NN + q0 + 2 * n2;
            float2 xv = *(const float2*)&x[gi];
            float2 res;
            res.x = fmaf(vx, sInv[2 * n2], xv.x);
            res.y = fmaf(vy, sInv[2 * n2 + 1], xv.y);
            *(float2*)&out[gi] = res;
        }
    }
}

extern "C" void kernel_launch(void* const* d_in, const int* in_sizes, int n_in,
                              void* d_out, int out_size) {
    const float* x     = (const float*)d_in[0];
    const float* ctx   = (const float*)d_in[1];
    const float* Wq    = (const float*)d_in[2];
    const float* bq    = (const float*)d_in[3];
    const float* Wk    = (const float*)d_in[4];
    const float* bk    = (const float*)d_in[5];
    const float* Wv    = (const float*)d_in[6];
    const float* bv    = (const float*)d_in[7];
    const float* gamma = (const float*)d_in[8];
    float* out = (float*)d_out;

    proj_kernel<<<512, 256>>>(x, ctx, Wq, bq, Wk, bk, Wv, bv);
    attn_kernel<<<dim3(64, BB, MSPLIT), 256>>>(x, gamma, out);
}

// round 14
// speedup vs baseline: 1.0499x; 1.0499x over previous
#include <cuda_runtime.h>
#include <cuda_bf16.h>

#define NN 4096
#define BB 2
#define CC 64
#define MSPLIT 2

typedef unsigned int u32;

// Scratch
__device__ __nv_bfloat16 g_qh[(size_t)BB * NN * 8];           // [b][n][8c] (q pre-scaled by log2e)
__device__ __nv_bfloat16 g_kh[(size_t)BB * NN * 8];           // [b][m][8c]
__device__ __nv_bfloat16 g_vh[(size_t)BB * CC * NN];          // [b][c][m]
__device__ __nv_bfloat16 g_po[(size_t)MSPLIT * BB * CC * NN]; // partial O [s][b][c][n]
__device__ float g_prs[(size_t)MSPLIT * BB * NN];             // partial rowsum [s][b][n]
__device__ int g_tk[BB * 64];                                 // tickets (mod-MSPLIT)

__device__ __forceinline__ u32 packbf(float lo, float hi) {
    u32 r;
    asm("cvt.rn.bf16x2.f32 %0, %1, %2;" : "=r"(r) : "f"(hi), "f"(lo));
    return r;
}
__device__ __forceinline__ float2 unpackbf(u32 v) {
    __nv_bfloat162 h = *(__nv_bfloat162*)&v;
    return make_float2(__bfloat162float(h.x), __bfloat162float(h.y));
}
__device__ __forceinline__ float ex2(float x) {
    float y;
    asm("ex2.approx.ftz.f32 %0, %1;" : "=f"(y) : "f"(x));
    return y;
}

__device__ __forceinline__ void mma_bf16_k8(float d[4], u32 a0, u32 a1, u32 b0) {
    asm("mma.sync.aligned.m16n8k8.row.col.f32.bf16.bf16.f32 "
        "{%0,%1,%2,%3}, {%4,%5}, {%6}, {%0,%1,%2,%3};"
        : "+f"(d[0]), "+f"(d[1]), "+f"(d[2]), "+f"(d[3])
        : "r"(a0), "r"(a1), "r"(b0));
}
__device__ __forceinline__ void mma_bf16_k16(float d[4], u32 a0, u32 a1, u32 a2, u32 a3,
                                             u32 b0, u32 b1) {
    asm("mma.sync.aligned.m16n8k16.row.col.f32.bf16.bf16.f32 "
        "{%0,%1,%2,%3}, {%4,%5,%6,%7}, {%8,%9}, {%0,%1,%2,%3};"
        : "+f"(d[0]), "+f"(d[1]), "+f"(d[2]), "+f"(d[3])
        : "r"(a0), "r"(a1), "r"(a2), "r"(a3), "r"(b0), "r"(b1));
}
__device__ __forceinline__ void ldsm_x4(u32& r0, u32& r1, u32& r2, u32& r3, u32 saddr) {
    asm volatile("ldmatrix.sync.aligned.m8n8.x4.shared.b16 {%0,%1,%2,%3}, [%4];"
                 : "=r"(r0), "=r"(r1), "=r"(r2), "=r"(r3) : "r"(saddr));
}
__device__ __forceinline__ void cp16(u32 dst, const void* src) {
    asm volatile("cp.async.cg.shared.global [%0], [%1], 16;" :: "r"(dst), "l"(src));
}
__device__ __forceinline__ void cp4(u32 dst, const void* src) {
    asm volatile("cp.async.ca.shared.global [%0], [%1], 4;" :: "r"(dst), "l"(src));
}
__device__ __forceinline__ void cp_commit() { asm volatile("cp.async.commit_group;"); }
__device__ __forceinline__ void cp_wait0() { asm volatile("cp.async.wait_group 0;"); }
__device__ __forceinline__ void cp_wait2() { asm volatile("cp.async.wait_group 2;"); }

// ---------------------------------------------------------------------------
// Fused projection kernel, 768 CTAs, work-balanced:
//   CTAs [0,256):   q/k, 32-column tiles (light)
//   CTAs [256,768): v, 16-column tiles (512 CTAs -> fine-grain balance)
// ---------------------------------------------------------------------------
__global__ __launch_bounds__(256) void proj_kernel(const float* __restrict__ x,
                                                   const float* __restrict__ ctx,
                                                   const float* __restrict__ Wq,
                                                   const float* __restrict__ bq,
                                                   const float* __restrict__ Wk,
                                                   const float* __restrict__ bk,
                                                   const float* __restrict__ Wv,
                                                   const float* __restrict__ bv) {
    const int tid = threadIdx.x;
    const float LOG2E = 1.4426950408889634f;

    if (blockIdx.x < 256) {
        const int idx = blockIdx.x;
        const int b = idx >> 7;
        const int n0 = (idx & 127) * 32;
        __shared__ float sx[64][36];
        __shared__ float sct[64][36];
        __shared__ float sW[16][64];
        __shared__ float sb[16];

        for (int i = tid; i < 512; i += 256) {
            sW[i >> 6][i & 63] = Wq[i] * LOG2E;
            sW[8 + (i >> 6)][i & 63] = Wk[i];
        }
        if (tid < 8) { sb[tid] = bq[tid] * LOG2E; sb[8 + tid] = bk[tid]; }
#pragma unroll
        for (int k = 0; k < 2; k++) {
            int i = k * 256 + tid;
            int r = i >> 3, f4 = (i & 7) * 4;
            *(float4*)&sx[r][f4] = *(const float4*)&x[((size_t)b * CC + r) * NN + n0 + f4];
            *(float4*)&sct[r][f4] = *(const float4*)&ctx[((size_t)b * CC + r) * NN + n0 + f4];
        }
        __syncthreads();

        const int n = tid & 31;
        const int og = tid >> 5;
        const bool isk = og >= 4;
        const int r2 = 2 * (og & 3);
        const int wrow = (isk ? 8 : 0) + r2;
        float a0 = sb[wrow], a1 = sb[wrow + 1];
#pragma unroll
        for (int c = 0; c < 64; c++) {
            float v = isk ? sct[c][n] : sx[c][n];
            a0 = fmaf(sW[wrow][c], v, a0);
            a1 = fmaf(sW[wrow + 1][c], v, a1);
        }
        __nv_bfloat16* dst = isk ? g_kh : g_qh;
        *(u32*)(dst + ((size_t)b * NN + n0 + n) * 8 + r2) = packbf(a0, a1);
    } else {
        const int vi = blockIdx.x - 256;      // 0..511
        const int b = vi >> 8;
        const int m0 = (vi & 255) * 16;
        __shared__ float sC[64][16];
        __shared__ float sWv[64][68];          // [cc][c]
        __shared__ float sbv[64];

        for (int i = tid; i < 4096; i += 256) sWv[i & 63][i >> 6] = Wv[i];
        if (tid < 64) sbv[tid] = bv[tid];
        {
            int r = tid >> 2, f4 = (tid & 3) * 4;
            *(float4*)&sC[r][f4] = *(const float4*)&ctx[((size_t)b * CC + r) * NN + m0 + f4];
        }
        __syncthreads();

        const int m2 = (tid & 7) * 2;          // 2 m's
        const int c2 = (tid >> 3) * 2;         // 2 c's
        float a00 = sbv[c2], a01 = sbv[c2];
        float a10 = sbv[c2 + 1], a11 = sbv[c2 + 1];
#pragma unroll
        for (int cc = 0; cc < 64; cc++) {
            float2 vm = *(const float2*)&sC[cc][m2];
            float2 wv = *(const float2*)&sWv[cc][c2];
            a00 = fmaf(wv.x, vm.x, a00);
            a01 = fmaf(wv.x, vm.y, a01);
            a10 = fmaf(wv.y, vm.x, a10);
            a11 = fmaf(wv.y, vm.y, a11);
        }
        *(u32*)(g_vh + ((size_t)b * CC + c2) * NN + m0 + m2) = packbf(a00, a01);
        *(u32*)(g_vh + ((size_t)b * CC + c2 + 1) * NN + m0 + m2) = packbf(a10, a11);
    }
}

// ---------------------------------------------------------------------------
// Attention (R10 verbatim — best total): bf16 mma, 4-stage cp.async ring
// (wait_group 2), hoisted S-mmas, CTA-wide barrier, MSPLIT=2.
//   grid (64 qtiles, B, 2), 256 threads = 8 warps, 2 CTAs/SM.
// ---------------------------------------------------------------------------
__global__ __launch_bounds__(256, 2) void attn_kernel(const float* __restrict__ x,
                                                      const float* __restrict__ gammap,
                                                      float* __restrict__ out) {
    __shared__ __nv_bfloat16 sQ[64][8];
    __shared__ __nv_bfloat16 sK[4][64][8];
    __shared__ __align__(16) char svbuf[4][64 * 144];   // sV 4-stage ring / sO alias
    __shared__ float sRS[64][2];
    __shared__ float sInv[64];
    __shared__ int sFlag;
    float (*sO)[65] = (float (*)[65])svbuf;

    const int tid = threadIdx.x;
    const int b = blockIdx.y;
    const int q0 = blockIdx.x * 64;
    const int s = blockIdx.z;
    const int ck0 = s * 32;
    const int lane = tid & 31;
    const int g = lane >> 2;
    const int t = lane & 3;
    const int qT = (tid >> 5) & 3;
    const int h = tid >> 7;
    const int r = 16 * qT + g;

    const char* gk = (const char*)g_kh + (size_t)b * NN * 8 * 2;
    const char* gv = (const char*)g_vh + (size_t)b * CC * NN * 2;

    ((u32*)sQ)[tid] = ((const u32*)((const char*)g_qh + ((size_t)b * NN + q0) * 16))[tid];

    // shared-space addresses
    const u32 svb = (u32)__cvta_generic_to_shared(svbuf);
    const u32 skb = (u32)__cvta_generic_to_shared(sK);
    const u32 vA = svb + lane * 144 + 64 * h;        // ldmatrix: c = lane,    m base 32h
    const u32 vB = vA + 32 * 144;                    //           c = 32+lane
    const u32 kA = skb + (32 * h + lane) * 16;       //           m = 32h+lane
    // cp.async dst/src fixed per thread
    const u32 kDst = skb + tid * 4;
    const u32 vDst = svb + (tid >> 2) * 144 + (tid & 3) * 32;
    const char* kSrc = gk + tid * 4;
    const char* vSrc = gv + ((size_t)(tid >> 2) * NN) * 2 + (tid & 3) * 32;

    // Prologue: stage chunks ck0, ck0+1, ck0+2 into buffers 0,1,2
#pragma unroll
    for (int p = 0; p < 3; p++) {
        size_t off = (size_t)(ck0 + p) * 64;
        cp4(kDst + p * 1024, kSrc + off * 16);
        cp16(vDst + p * 9216, vSrc + off * 2);
        cp16(vDst + p * 9216 + 16, vSrc + off * 2 + 16);
        cp_commit();
    }

    // sQ is written cross-warp: barrier before reading Q fragments.
    __syncthreads();

    const u32 qa0 = *(const u32*)((const char*)sQ + r * 16 + t * 4);
    const u32 qa1 = *(const u32*)((const char*)sQ + (r + 8) * 16 + t * 4);

    float oC[8][4];
#pragma unroll
    for (int i = 0; i < 8; i++)
#pragma unroll
        for (int j = 0; j < 4; j++) oC[i][j] = 0.0f;
    float rs0 = 0.0f, rs1 = 0.0f;

    for (int ck = 0; ck < 32; ck++) {
        const int buf = ck & 3;
        const u32 vOff = buf * 9216;
        const u32 kOff = buf * 1024;

        // Wait until chunk ck's group is resident (2 groups of slack), sync.
        if (ck < 30) cp_wait2(); else cp_wait0();
        __syncthreads();

        // Stage chunk ck+3 into buffer (ck+3)&3 (freed at ck-1, barrier above)
        if (ck < 29) {
            size_t off = (size_t)(ck0 + ck + 3) * 64;
            const u32 nb = (ck + 3) & 3;
            cp4(kDst + nb * 1024, kSrc + off * 16);
            cp16(vDst + nb * 9216, vSrc + off * 2);
            cp16(vDst + nb * 9216 + 16, vSrc + off * 2 + 16);
            cp_commit();
        }

        // K b-frags + all 4 S-mmas up front (independent -> fill tensor queue)
        u32 kb[4];
        ldsm_x4(kb[0], kb[1], kb[2], kb[3], kA + kOff);
        float e[4][4];
#pragma unroll
        for (int j = 0; j < 4; j++) {
            e[j][0] = e[j][1] = e[j][2] = e[j][3] = 0.0f;
            mma_bf16_k8(e[j], qa0, qa1, kb[j]);
        }

        // ---- per-ks: V ldsm, ex2, O-mmas ----
#pragma unroll
        for (int ks = 0; ks < 2; ks++) {
            u32 bl[4][2], bh[4][2];
            {
                u32 base = vOff + 32 * ks;
                ldsm_x4(bl[0][0], bl[1][0], bl[2][0], bl[3][0], vA + base);
                ldsm_x4(bl[0][1], bl[1][1], bl[2][1], bl[3][1], vA + base + 16);
                ldsm_x4(bh[0][0], bh[1][0], bh[2][0], bh[3][0], vB + base);
                ldsm_x4(bh[0][1], bh[1][1], bh[2][1], bh[3][1], vB + base + 16);
            }
            float* e0 = e[2 * ks];
            float* e1 = e[2 * ks + 1];
            float p00 = ex2(e0[0]), p01 = ex2(e0[1]);
            float p02 = ex2(e0[2]), p03 = ex2(e0[3]);
            float p10 = ex2(e1[0]), p11 = ex2(e1[1]);
            float p12 = ex2(e1[2]), p13 = ex2(e1[3]);
            rs0 += p00 + p01 + p10 + p11;
            rs1 += p02 + p03 + p12 + p13;
            u32 a0 = packbf(p00, p01);
            u32 a1 = packbf(p02, p03);
            u32 a2 = packbf(p10, p11);
            u32 a3 = packbf(p12, p13);

#pragma unroll
            for (int cT = 0; cT < 4; cT++)
                mma_bf16_k16(oC[cT], a0, a1, a2, a3, bl[cT][0], bl[cT][1]);
#pragma unroll
            for (int cT = 0; cT < 4; cT++)
                mma_bf16_k16(oC[4 + cT], a0, a1, a2, a3, bh[cT][0], bh[cT][1]);
        }
    }

    // Rowsums
    rs0 += __shfl_xor_sync(0xffffffffu, rs0, 1);
    rs0 += __shfl_xor_sync(0xffffffffu, rs0, 2);
    rs1 += __shfl_xor_sync(0xffffffffu, rs1, 1);
    rs1 += __shfl_xor_sync(0xffffffffu, rs1, 2);
    if (t == 0) {
        sRS[r][h] = rs0;
        sRS[r + 8][h] = rs1;
    }
    __syncthreads();   // all compute done; sV ring dead; sO may be written

    // Cross-h O reduce into sO
    if (h == 0) {
#pragma unroll
        for (int cT = 0; cT < 8; cT++) {
            int c = 8 * cT + 2 * t;
            sO[r][c] = oC[cT][0];
            sO[r][c + 1] = oC[cT][1];
            sO[r + 8][c] = oC[cT][2];
            sO[r + 8][c + 1] = oC[cT][3];
        }
    }
    __syncthreads();
    if (h == 1) {
#pragma unroll
        for (int cT = 0; cT < 8; cT++) {
            int c = 8 * cT + 2 * t;
            sO[r][c] += oC[cT][0];
            sO[r][c + 1] += oC[cT][1];
            sO[r + 8][c] += oC[cT][2];
            sO[r + 8][c + 1] += oC[cT][3];
        }
    }
    __syncthreads();

    // Partial rowsum + partial bf16 O [s][b][c][n]
    if (tid < 64)
        g_prs[((size_t)s * BB + b) * NN + q0 + tid] = sRS[tid][0] + sRS[tid][1];
    {
        u32* po = (u32*)g_po + ((size_t)s * BB + b) * (CC * NN / 2);
#pragma unroll
        for (int k = 0; k < 8; k++) {
            int i = k * 256 + tid;
            int c = i >> 5, n2 = i & 31;
            po[(size_t)c * (NN / 2) + q0 / 2 + n2] = packbf(sO[2 * n2][c], sO[2 * n2 + 1][c]);
        }
    }

    // Ticket: last CTA of this (tile, b) performs the combine
    __threadfence();
    __syncthreads();
    if (tid == 0) sFlag = ((atomicAdd(&g_tk[b * 64 + blockIdx.x], 1) & (MSPLIT - 1)) == MSPLIT - 1);
    __syncthreads();

    if (sFlag) {
        __threadfence();
        if (tid < 64) {
            float rsum = 0.0f;
#pragma unroll
            for (int ss = 0; ss < MSPLIT; ss++)
                rsum += g_prs[((size_t)ss * BB + b) * NN + q0 + tid];
            sInv[tid] = gammap[0] / rsum;
        }
        __syncthreads();
#pragma unroll
        for (int k = 0; k < 8; k++) {
            int i = k * 256 + tid;
            int c = i >> 5, n2 = i & 31;
            size_t pi = (size_t)c * (NN / 2) + q0 / 2 + n2;
            float vx = 0.0f, vy = 0.0f;
#pragma unroll
            for (int ss = 0; ss < MSPLIT; ss++) {
                float2 v = unpackbf(((const u32*)g_po + ((size_t)ss * BB + b) * (CC * NN / 2))[pi]);
                vx += v.x;
                vy += v.y;
            }
            size_t gi = ((size_t)b * CC + c) * NN + q0 + 2 * n2;
            float2 xv = *(const float2*)&x[gi];
            float2 res;
            res.x = fmaf(vx, sInv[2 * n2], xv.x);
            res.y = fmaf(vy, sInv[2 * n2 + 1], xv.y);
            *(float2*)&out[gi] = res;
        }
    }
}

extern "C" void kernel_launch(void* const* d_in, const int* in_sizes, int n_in,
                              void* d_out, int out_size) {
    const float* x     = (const float*)d_in[0];
    const float* ctx   = (const float*)d_in[1];
    const float* Wq    = (const float*)d_in[2];
    const float* bq    = (const float*)d_in[3];
    const float* Wk    = (const float*)d_in[4];
    const float* bk    = (const float*)d_in[5];
    const float* Wv    = (const float*)d_in[6];
    const float* bv    = (const float*)d_in[7];
    const float* gamma = (const float*)d_in[8];
    float* out = (float*)d_out;

    proj_kernel<<<768, 256>>>(x, ctx, Wq, bq, Wk, bk, Wv, bv);
    attn_kernel<<<dim3(64, BB, MSPLIT), 256>>>(x, gamma, out);
}

// round 15
// speedup vs baseline: 1.1104x; 1.0576x over previous
#include <cuda_runtime.h>
#include <cuda_bf16.h>

#define NN 4096
#define BB 2
#define CC 64
#define MSPLIT 2
#define NCTA (64 * BB * MSPLIT)   // 256 CTAs, all resident (<= 296 slots at occ 2)

typedef unsigned int u32;

// Scratch
__device__ __nv_bfloat16 g_qh[(size_t)BB * NN * 8];           // [b][n][8c] (q pre-scaled by log2e)
__device__ __nv_bfloat16 g_kh[(size_t)BB * NN * 8];           // [b][m][8c]
__device__ __nv_bfloat16 g_vh[(size_t)BB * CC * NN];          // [b][c][m]
__device__ __nv_bfloat16 g_po[(size_t)MSPLIT * BB * CC * NN]; // partial O [s][b][c][n]
__device__ float g_prs[(size_t)MSPLIT * BB * NN];             // partial rowsum [s][b][n]
__device__ int g_tk[BB * 64];                                 // combine tickets (mod-MSPLIT)
__device__ int g_pbar;                                        // grid barrier (monotonic)

__device__ __forceinline__ u32 packbf(float lo, float hi) {
    u32 r;
    asm("cvt.rn.bf16x2.f32 %0, %1, %2;" : "=r"(r) : "f"(hi), "f"(lo));
    return r;
}
__device__ __forceinline__ float2 unpackbf(u32 v) {
    __nv_bfloat162 h = *(__nv_bfloat162*)&v;
    return make_float2(__bfloat162float(h.x), __bfloat162float(h.y));
}
__device__ __forceinline__ float ex2(float x) {
    float y;
    asm("ex2.approx.ftz.f32 %0, %1;" : "=f"(y) : "f"(x));
    return y;
}

__device__ __forceinline__ void mma_bf16_k8(float d[4], u32 a0, u32 a1, u32 b0) {
    asm("mma.sync.aligned.m16n8k8.row.col.f32.bf16.bf16.f32 "
        "{%0,%1,%2,%3}, {%4,%5}, {%6}, {%0,%1,%2,%3};"
        : "+f"(d[0]), "+f"(d[1]), "+f"(d[2]), "+f"(d[3])
        : "r"(a0), "r"(a1), "r"(b0));
}
__device__ __forceinline__ void mma_bf16_k16(float d[4], u32 a0, u32 a1, u32 a2, u32 a3,
                                             u32 b0, u32 b1) {
    asm("mma.sync.aligned.m16n8k16.row.col.f32.bf16.bf16.f32 "
        "{%0,%1,%2,%3}, {%4,%5,%6,%7}, {%8,%9}, {%0,%1,%2,%3};"
        : "+f"(d[0]), "+f"(d[1]), "+f"(d[2]), "+f"(d[3])
        : "r"(a0), "r"(a1), "r"(a2), "r"(a3), "r"(b0), "r"(b1));
}
__device__ __forceinline__ void ldsm_x4(u32& r0, u32& r1, u32& r2, u32& r3, u32 saddr) {
    asm volatile("ldmatrix.sync.aligned.m8n8.x4.shared.b16 {%0,%1,%2,%3}, [%4];"
                 : "=r"(r0), "=r"(r1), "=r"(r2), "=r"(r3) : "r"(saddr));
}
__device__ __forceinline__ void cp16(u32 dst, const void* src) {
    asm volatile("cp.async.cg.shared.global [%0], [%1], 16;" :: "r"(dst), "l"(src));
}
__device__ __forceinline__ void cp4(u32 dst, const void* src) {
    asm volatile("cp.async.ca.shared.global [%0], [%1], 4;" :: "r"(dst), "l"(src));
}
__device__ __forceinline__ void cp_commit() { asm volatile("cp.async.commit_group;"); }
__device__ __forceinline__ void cp_wait0() { asm volatile("cp.async.wait_group 0;"); }
__device__ __forceinline__ void cp_wait2() { asm volatile("cp.async.wait_group 2;"); }

// ---------------------------------------------------------------------------
// Single fused kernel: phase 0 = projections (each CTA does one qk tile and
// one v tile, overlaid on the sV-ring smem), grid barrier (all 256 CTAs are
// co-resident by the launch_bounds(256,2) contract: 256 <= 2*148), then the
// R10 attention mainloop verbatim.
// ---------------------------------------------------------------------------
__global__ __launch_bounds__(256, 2) void fused_kernel(const float* __restrict__ x,
                                                       const float* __restrict__ ctx,
                                                       const float* __restrict__ Wq,
                                                       const float* __restrict__ bq,
                                                       const float* __restrict__ Wk,
                                                       const float* __restrict__ bk,
                                                       const float* __restrict__ Wv,
                                                       const float* __restrict__ bv,
                                                       const float* __restrict__ gammap,
                                                       float* __restrict__ out) {
    __shared__ __nv_bfloat16 sQ[64][8];
    __shared__ __nv_bfloat16 sK[4][64][8];
    __shared__ __align__(16) char svbuf[4][64 * 144];   // sV ring / sO / proj overlay
    __shared__ float sRS[64][2];
    __shared__ float sInv[64];
    __shared__ int sFlag;
    float (*sO)[65] = (float (*)[65])svbuf;

    const int tid = threadIdx.x;
    const int b = blockIdx.y;
    const int q0 = blockIdx.x * 64;
    const int s = blockIdx.z;
    const int ck0 = s * 32;
    const int lane = tid & 31;
    const int g = lane >> 2;
    const int t = lane & 3;
    const int qT = (tid >> 5) & 3;
    const int h = tid >> 7;
    const int r = 16 * qT + g;
    const float LOG2E = 1.4426950408889634f;

    // ===================== PHASE 0: projections =====================
    {
        const int cid = blockIdx.x + 64 * b + 128 * s;   // [0,256) bijective
        const int pb = cid >> 7;
        const int pn0 = (cid & 127) * 32;
        char* base = &svbuf[0][0];

        // ---- qk tile (32 cols): q rows pre-scaled by log2e ----
        {
            float (*sx)[36] = (float (*)[36])base;
            float (*sct)[36] = (float (*)[36])(base + 9216);
            float (*sW)[64] = (float (*)[64])(base + 18432);
            float* sb = (float*)(base + 22528);

            for (int i = tid; i < 512; i += 256) {
                sW[i >> 6][i & 63] = Wq[i] * LOG2E;
                sW[8 + (i >> 6)][i & 63] = Wk[i];
            }
            if (tid < 8) { sb[tid] = bq[tid] * LOG2E; sb[8 + tid] = bk[tid]; }
#pragma unroll
            for (int k = 0; k < 2; k++) {
                int i = k * 256 + tid;
                int rr = i >> 3, f4 = (i & 7) * 4;
                *(float4*)&sx[rr][f4] = *(const float4*)&x[((size_t)pb * CC + rr) * NN + pn0 + f4];
                *(float4*)&sct[rr][f4] = *(const float4*)&ctx[((size_t)pb * CC + rr) * NN + pn0 + f4];
            }
            __syncthreads();

            const int n = tid & 31;
            const int og = tid >> 5;
            const bool isk = og >= 4;
            const int r2 = 2 * (og & 3);
            const int wrow = (isk ? 8 : 0) + r2;
            float a0 = sb[wrow], a1 = sb[wrow + 1];
#pragma unroll
            for (int c = 0; c < 64; c++) {
                float v = isk ? sct[c][n] : sx[c][n];
                a0 = fmaf(sW[wrow][c], v, a0);
                a1 = fmaf(sW[wrow + 1][c], v, a1);
            }
            __nv_bfloat16* dst = isk ? g_kh : g_qh;
            *(u32*)(dst + ((size_t)pb * NN + pn0 + n) * 8 + r2) = packbf(a0, a1);
        }
        __syncthreads();   // reuse overlay region

        // ---- v tile (32 cols): 4c x 2m per thread ----
        {
            float (*sC)[36] = (float (*)[36])base;
            float (*sWv)[68] = (float (*)[68])(base + 9216);
            float* sbv = (float*)(base + 26624);

            for (int i = tid; i < 4096; i += 256) sWv[i & 63][i >> 6] = Wv[i];
            if (tid < 64) sbv[tid] = bv[tid];
#pragma unroll
            for (int k = 0; k < 2; k++) {
                int i = k * 256 + tid;
                int rr = i >> 3, f4 = (i & 7) * 4;
                *(float4*)&sC[rr][f4] = *(const float4*)&ctx[((size_t)pb * CC + rr) * NN + pn0 + f4];
            }
            __syncthreads();

            const int m2 = (tid & 15) * 2;
            const int cg = (tid >> 4) * 4;
            float acc[4][2];
#pragma unroll
            for (int j = 0; j < 4; j++) acc[j][0] = acc[j][1] = sbv[cg + j];
#pragma unroll
            for (int cc = 0; cc < 64; cc++) {
                float2 vm = *(const float2*)&sC[cc][m2];
                float4 wv = *(const float4*)&sWv[cc][cg];
                float ww[4] = {wv.x, wv.y, wv.z, wv.w};
#pragma unroll
                for (int j = 0; j < 4; j++) {
                    acc[j][0] = fmaf(ww[j], vm.x, acc[j][0]);
                    acc[j][1] = fmaf(ww[j], vm.y, acc[j][1]);
                }
            }
#pragma unroll
            for (int j = 0; j < 4; j++)
                *(u32*)(g_vh + ((size_t)pb * CC + cg + j) * NN + pn0 + m2) = packbf(acc[j][0], acc[j][1]);
        }

        // ---- grid barrier (monotonic epoch ticket; replay-safe) ----
        __threadfence();
        __syncthreads();
        if (tid == 0) {
            int my = atomicAdd(&g_pbar, 1);
            int target = (my / NCTA + 1) * NCTA;
            int cur;
            do {
                asm volatile("ld.global.cg.b32 %0, [%1];" : "=r"(cur) : "l"(&g_pbar));
                if (cur < target) __nanosleep(64);
            } while (cur < target);
        }
        __syncthreads();
    }

    // ===================== PHASE 1: attention (R10) =====================
    const char* gk = (const char*)g_kh + (size_t)b * NN * 8 * 2;
    const char* gv = (const char*)g_vh + (size_t)b * CC * NN * 2;

    ((u32*)sQ)[tid] = ((const u32*)((const char*)g_qh + ((size_t)b * NN + q0) * 16))[tid];

    const u32 svb = (u32)__cvta_generic_to_shared(svbuf);
    const u32 skb = (u32)__cvta_generic_to_shared(sK);
    const u32 vA = svb + lane * 144 + 64 * h;
    const u32 vB = vA + 32 * 144;
    const u32 kA = skb + (32 * h + lane) * 16;
    const u32 kDst = skb + tid * 4;
    const u32 vDst = svb + (tid >> 2) * 144 + (tid & 3) * 32;
    const char* kSrc = gk + tid * 4;
    const char* vSrc = gv + ((size_t)(tid >> 2) * NN) * 2 + (tid & 3) * 32;

    // Prologue: stage chunks ck0..ck0+2 into buffers 0..2
#pragma unroll
    for (int p = 0; p < 3; p++) {
        size_t off = (size_t)(ck0 + p) * 64;
        cp4(kDst + p * 1024, kSrc + off * 16);
        cp16(vDst + p * 9216, vSrc + off * 2);
        cp16(vDst + p * 9216 + 16, vSrc + off * 2 + 16);
        cp_commit();
    }

    // sQ written cross-warp: barrier before Q fragment reads.
    __syncthreads();

    const u32 qa0 = *(const u32*)((const char*)sQ + r * 16 + t * 4);
    const u32 qa1 = *(const u32*)((const char*)sQ + (r + 8) * 16 + t * 4);

    float oC[8][4];
#pragma unroll
    for (int i = 0; i < 8; i++)
#pragma unroll
        for (int j = 0; j < 4; j++) oC[i][j] = 0.0f;
    float rs0 = 0.0f, rs1 = 0.0f;

    for (int ck = 0; ck < 32; ck++) {
        const int buf = ck & 3;
        const u32 vOff = buf * 9216;
        const u32 kOff = buf * 1024;

        if (ck < 30) cp_wait2(); else cp_wait0();
        __syncthreads();

        if (ck < 29) {
            size_t off = (size_t)(ck0 + ck + 3) * 64;
            const u32 nb = (ck + 3) & 3;
            cp4(kDst + nb * 1024, kSrc + off * 16);
            cp16(vDst + nb * 9216, vSrc + off * 2);
            cp16(vDst + nb * 9216 + 16, vSrc + off * 2 + 16);
            cp_commit();
        }

        u32 kb[4];
        ldsm_x4(kb[0], kb[1], kb[2], kb[3], kA + kOff);
        float e[4][4];
#pragma unroll
        for (int j = 0; j < 4; j++) {
            e[j][0] = e[j][1] = e[j][2] = e[j][3] = 0.0f;
            mma_bf16_k8(e[j], qa0, qa1, kb[j]);
        }

#pragma unroll
        for (int ks = 0; ks < 2; ks++) {
            u32 bl[4][2], bh[4][2];
            {
                u32 base2 = vOff + 32 * ks;
                ldsm_x4(bl[0][0], bl[1][0], bl[2][0], bl[3][0], vA + base2);
                ldsm_x4(bl[0][1], bl[1][1], bl[2][1], bl[3][1], vA + base2 + 16);
                ldsm_x4(bh[0][0], bh[1][0], bh[2][0], bh[3][0], vB + base2);
                ldsm_x4(bh[0][1], bh[1][1], bh[2][1], bh[3][1], vB + base2 + 16);
            }
            float* e0 = e[2 * ks];
            float* e1 = e[2 * ks + 1];
            float p00 = ex2(e0[0]), p01 = ex2(e0[1]);
            float p02 = ex2(e0[2]), p03 = ex2(e0[3]);
            float p10 = ex2(e1[0]), p11 = ex2(e1[1]);
            float p12 = ex2(e1[2]), p13 = ex2(e1[3]);
            rs0 += p00 + p01 + p10 + p11;
            rs1 += p02 + p03 + p12 + p13;
            u32 a0 = packbf(p00, p01);
            u32 a1 = packbf(p02, p03);
            u32 a2 = packbf(p10, p11);
            u32 a3 = packbf(p12, p13);

#pragma unroll
            for (int cT = 0; cT < 4; cT++)
                mma_bf16_k16(oC[cT], a0, a1, a2, a3, bl[cT][0], bl[cT][1]);
#pragma unroll
            for (int cT = 0; cT < 4; cT++)
                mma_bf16_k16(oC[4 + cT], a0, a1, a2, a3, bh[cT][0], bh[cT][1]);
        }
    }

    // Rowsums
    rs0 += __shfl_xor_sync(0xffffffffu, rs0, 1);
    rs0 += __shfl_xor_sync(0xffffffffu, rs0, 2);
    rs1 += __shfl_xor_sync(0xffffffffu, rs1, 1);
    rs1 += __shfl_xor_sync(0xffffffffu, rs1, 2);
    if (t == 0) {
        sRS[r][h] = rs0;
        sRS[r + 8][h] = rs1;
    }
    __syncthreads();   // sV ring dead; sO may be written

    if (h == 0) {
#pragma unroll
        for (int cT = 0; cT < 8; cT++) {
            int c = 8 * cT + 2 * t;
            sO[r][c] = oC[cT][0];
            sO[r][c + 1] = oC[cT][1];
            sO[r + 8][c] = oC[cT][2];
            sO[r + 8][c + 1] = oC[cT][3];
        }
    }
    __syncthreads();
    if (h == 1) {
#pragma unroll
        for (int cT = 0; cT < 8; cT++) {
            int c = 8 * cT + 2 * t;
            sO[r][c] += oC[cT][0];
            sO[r][c + 1] += oC[cT][1];
            sO[r + 8][c] += oC[cT][2];
            sO[r + 8][c + 1] += oC[cT][3];
        }
    }
    __syncthreads();

    // Partial rowsum + partial bf16 O [s][b][c][n]
    if (tid < 64)
        g_prs[((size_t)s * BB + b) * NN + q0 + tid] = sRS[tid][0] + sRS[tid][1];
    {
        u32* po = (u32*)g_po + ((size_t)s * BB + b) * (CC * NN / 2);
#pragma unroll
        for (int k = 0; k < 8; k++) {
            int i = k * 256 + tid;
            int c = i >> 5, n2 = i & 31;
            po[(size_t)c * (NN / 2) + q0 / 2 + n2] = packbf(sO[2 * n2][c], sO[2 * n2 + 1][c]);
        }
    }

    // Ticket: last CTA of this (tile, b) performs the combine
    __threadfence();
    __syncthreads();
    if (tid == 0) sFlag = ((atomicAdd(&g_tk[b * 64 + blockIdx.x], 1) & (MSPLIT - 1)) == MSPLIT - 1);
    __syncthreads();

    if (sFlag) {
        __threadfence();
        if (tid < 64) {
            float rsum = 0.0f;
#pragma unroll
            for (int ss = 0; ss < MSPLIT; ss++)
                rsum += g_prs[((size_t)ss * BB + b) * NN + q0 + tid];
            sInv[tid] = gammap[0] / rsum;
        }
        __syncthreads();
#pragma unroll
        for (int k = 0; k < 8; k++) {
            int i = k * 256 + tid;
            int c = i >> 5, n2 = i & 31;
            size_t pi = (size_t)c * (NN / 2) + q0 / 2 + n2;
            float vx = 0.0f, vy = 0.0f;
#pragma unroll
            for (int ss = 0; ss < MSPLIT; ss++) {
                float2 v = unpackbf(((const u32*)g_po + ((size_t)ss * BB + b) * (CC * NN / 2))[pi]);
                vx += v.x;
                vy += v.y;
            }
            size_t gi = ((size_t)b * CC + c) * NN + q0 + 2 * n2;
            float2 xv = *(const float2*)&x[gi];
            float2 res;
            res.x = fmaf(vx, sInv[2 * n2], xv.x);
            res.y = fmaf(vy, sInv[2 * n2 + 1], xv.y);
            *(float2*)&out[gi] = res;
        }
    }
}

extern "C" void kernel_launch(void* const* d_in, const int* in_sizes, int n_in,
                              void* d_out, int out_size) {
    const float* x     = (const float*)d_in[0];
    const float* ctx   = (const float*)d_in[1];
    const float* Wq    = (const float*)d_in[2];
    const float* bq    = (const float*)d_in[3];
    const float* Wk    = (const float*)d_in[4];
    const float* bk    = (const float*)d_in[5];
    const float* Wv    = (const float*)d_in[6];
    const float* bv    = (const float*)d_in[7];
    const float* gamma = (const float*)d_in[8];
    float* out = (float*)d_out;

    fused_kernel<<<dim3(64, BB, MSPLIT), 256>>>(x, ctx, Wq, bq, Wk, bk, Wv, bv, gamma, out);
}

// round 16
// speedup vs baseline: 1.1712x; 1.0548x over previous
#include <cuda_runtime.h>
#include <cuda_bf16.h>

#define NN 4096
#define BB 2
#define CC 64
#define MSPLIT 2
#define NCTA (64 * BB * MSPLIT)   // 256 CTAs, all resident (<= 296 slots at occ 2)

typedef unsigned int u32;

// Scratch
__device__ __nv_bfloat16 g_qh[(size_t)BB * NN * 8];           // [b][n][8c] (q pre-scaled by log2e)
__device__ __nv_bfloat16 g_kh[(size_t)BB * NN * 8];           // [b][m][8c]
__device__ __nv_bfloat16 g_vh[(size_t)BB * CC * NN];          // [b][c][m]
__device__ __nv_bfloat16 g_po[(size_t)MSPLIT * BB * CC * NN]; // partial O [s][b][c][n]
__device__ float g_prs[(size_t)MSPLIT * BB * NN];             // partial rowsum [s][b][n]
__device__ int g_tk[BB * 64];                                 // combine tickets (mod-MSPLIT)
__device__ int g_pbar;                                        // grid barrier (monotonic)

__device__ __forceinline__ u32 packbf(float lo, float hi) {
    u32 r;
    asm("cvt.rn.bf16x2.f32 %0, %1, %2;" : "=r"(r) : "f"(hi), "f"(lo));
    return r;
}
__device__ __forceinline__ float2 unpackbf(u32 v) {
    __nv_bfloat162 h = *(__nv_bfloat162*)&v;
    return make_float2(__bfloat162float(h.x), __bfloat162float(h.y));
}
__device__ __forceinline__ float ex2(float x) {
    float y;
    asm("ex2.approx.ftz.f32 %0, %1;" : "=f"(y) : "f"(x));
    return y;
}

__device__ __forceinline__ void mma_bf16_k8(float d[4], u32 a0, u32 a1, u32 b0) {
    asm("mma.sync.aligned.m16n8k8.row.col.f32.bf16.bf16.f32 "
        "{%0,%1,%2,%3}, {%4,%5}, {%6}, {%0,%1,%2,%3};"
        : "+f"(d[0]), "+f"(d[1]), "+f"(d[2]), "+f"(d[3])
        : "r"(a0), "r"(a1), "r"(b0));
}
__device__ __forceinline__ void mma_bf16_k16(float d[4], u32 a0, u32 a1, u32 a2, u32 a3,
                                             u32 b0, u32 b1) {
    asm("mma.sync.aligned.m16n8k16.row.col.f32.bf16.bf16.f32 "
        "{%0,%1,%2,%3}, {%4,%5,%6,%7}, {%8,%9}, {%0,%1,%2,%3};"
        : "+f"(d[0]), "+f"(d[1]), "+f"(d[2]), "+f"(d[3])
        : "r"(a0), "r"(a1), "r"(a2), "r"(a3), "r"(b0), "r"(b1));
}
__device__ __forceinline__ void ldsm_x4(u32& r0, u32& r1, u32& r2, u32& r3, u32 saddr) {
    asm volatile("ldmatrix.sync.aligned.m8n8.x4.shared.b16 {%0,%1,%2,%3}, [%4];"
                 : "=r"(r0), "=r"(r1), "=r"(r2), "=r"(r3) : "r"(saddr));
}
__device__ __forceinline__ void cp16(u32 dst, const void* src) {
    asm volatile("cp.async.cg.shared.global [%0], [%1], 16;" :: "r"(dst), "l"(src));
}
__device__ __forceinline__ void cp4(u32 dst, const void* src) {
    asm volatile("cp.async.ca.shared.global [%0], [%1], 4;" :: "r"(dst), "l"(src));
}
__device__ __forceinline__ void cp_commit() { asm volatile("cp.async.commit_group;"); }
__device__ __forceinline__ void cp_wait0() { asm volatile("cp.async.wait_group 0;"); }
__device__ __forceinline__ void cp_wait2() { asm volatile("cp.async.wait_group 2;"); }

// ---------------------------------------------------------------------------
// Single fused kernel. Phase 0 (rewritten): all staging async up-front, ONE
// barrier, qk+v computed back-to-back sharing the ctx tile. Grid barrier.
// Phase 1: R10 attention verbatim.
// ---------------------------------------------------------------------------
__global__ __launch_bounds__(256, 2) void fused_kernel(const float* __restrict__ x,
                                                       const float* __restrict__ ctx,
                                                       const float* __restrict__ Wq,
                                                       const float* __restrict__ bq,
                                                       const float* __restrict__ Wk,
                                                       const float* __restrict__ bk,
                                                       const float* __restrict__ Wv,
                                                       const float* __restrict__ bv,
                                                       const float* __restrict__ gammap,
                                                       float* __restrict__ out) {
    // Union region: phase0 overlay / [phase1: sV ring (36864) + sK (4096)]
    __shared__ __align__(16) char uni[4 * 9216 + 4 * 1024];
    __shared__ __nv_bfloat16 sQ[64][8];
    __shared__ float sRS[64][2];
    __shared__ float sInv[64];
    __shared__ int sFlag;
    float (*sO)[65] = (float (*)[65])uni;

    const int tid = threadIdx.x;
    const int b = blockIdx.y;
    const int q0 = blockIdx.x * 64;
    const int s = blockIdx.z;
    const int ck0 = s * 32;
    const int lane = tid & 31;
    const int g = lane >> 2;
    const int t = lane & 3;
    const int qT = (tid >> 5) & 3;
    const int h = tid >> 7;
    const int r = 16 * qT + g;
    const float LOG2E = 1.4426950408889634f;

    const u32 svb = (u32)__cvta_generic_to_shared(uni);

    // ===================== PHASE 0: projections =====================
    {
        const int cid = blockIdx.x + 64 * b + 128 * s;   // [0,256) bijective
        const int pb = cid >> 7;
        const int pn0 = (cid & 127) * 32;

        // Overlay layout (bytes from uni):
        //   sx   [64][36]f : 0      .. 9216
        //   sct  [64][36]f : 9216   .. 18432
        //   sWv  [64][68]f : 18432  .. 35840   (transposed [cc][c]; 272B rows)
        //   sW   [16][64]f : 35840  .. 39936
        //   sb   [16]f     : 39936  .. 40000
        //   sbv  [64]f     : 40000  .. 40256   (<= 40960)
        float (*sx)[36] = (float (*)[36])(uni);
        float (*sct)[36] = (float (*)[36])(uni + 9216);
        float (*sWv)[68] = (float (*)[68])(uni + 18432);
        float (*sW)[64] = (float (*)[64])(uni + 35840);
        float* sb = (float*)(uni + 39936);
        float* sbv = (float*)(uni + 40000);

        // --- issue ALL staging up front (max MLP, no barriers between) ---
        // x/ctx tiles via cp.async: 2 rows-halves per thread each
#pragma unroll
        for (int k = 0; k < 2; k++) {
            int row = k * 32 + (tid >> 3);
            int f4 = (tid & 7) * 4;
            u32 so = row * 144 + f4 * 4;
            cp16(svb + so, &x[((size_t)pb * CC + row) * NN + pn0 + f4]);
            cp16(svb + 9216 + so, &ctx[((size_t)pb * CC + row) * NN + pn0 + f4]);
        }
        cp_commit();
        // Wv transposed fill via float4 LDG (4 iters)
#pragma unroll
        for (int k = 0; k < 4; k++) {
            int i4 = k * 256 + tid;
            float4 w = ((const float4*)Wv)[i4];
            int i = i4 * 4;
            int c = i >> 6, cc = i & 63;
            sWv[cc][c] = w.x;
            sWv[cc + 1][c] = w.y;
            sWv[cc + 2][c] = w.z;
            sWv[cc + 3][c] = w.w;
        }
        // qk weights (pre-scaled q) + biases
#pragma unroll
        for (int k = 0; k < 2; k++) {
            int i = k * 256 + tid;
            sW[i >> 6][i & 63] = Wq[i] * LOG2E;
            sW[8 + (i >> 6)][i & 63] = Wk[i];
        }
        if (tid < 8) { sb[tid] = bq[tid] * LOG2E; sb[8 + tid] = bk[tid]; }
        if (tid < 64) sbv[tid] = bv[tid];
        cp_wait0();
        __syncthreads();   // the ONE phase-0 barrier

        // --- qk compute (2 rows/thread) ---
        {
            const int n = tid & 31;
            const int og = tid >> 5;
            const bool isk = og >= 4;
            const int r2 = 2 * (og & 3);
            const int wrow = (isk ? 8 : 0) + r2;
            float a0 = sb[wrow], a1 = sb[wrow + 1];
#pragma unroll
            for (int c = 0; c < 64; c++) {
                float v = isk ? sct[c][n] : sx[c][n];
                a0 = fmaf(sW[wrow][c], v, a0);
                a1 = fmaf(sW[wrow + 1][c], v, a1);
            }
            __nv_bfloat16* dst = isk ? g_kh : g_qh;
            *(u32*)(dst + ((size_t)pb * NN + pn0 + n) * 8 + r2) = packbf(a0, a1);
        }

        // --- v compute (4c x 2m/thread), reuses sct; no barrier needed ---
        {
            const int m2 = (tid & 15) * 2;
            const int cg = (tid >> 4) * 4;
            float acc[4][2];
#pragma unroll
            for (int j = 0; j < 4; j++) acc[j][0] = acc[j][1] = sbv[cg + j];
#pragma unroll
            for (int cc = 0; cc < 64; cc++) {
                float2 vm = *(const float2*)&sct[cc][m2];
                float4 wv = *(const float4*)&sWv[cc][cg];
                float ww[4] = {wv.x, wv.y, wv.z, wv.w};
#pragma unroll
                for (int j = 0; j < 4; j++) {
                    acc[j][0] = fmaf(ww[j], vm.x, acc[j][0]);
                    acc[j][1] = fmaf(ww[j], vm.y, acc[j][1]);
                }
            }
#pragma unroll
            for (int j = 0; j < 4; j++)
                *(u32*)(g_vh + ((size_t)pb * CC + cg + j) * NN + pn0 + m2) = packbf(acc[j][0], acc[j][1]);
        }

        // --- grid barrier (monotonic epoch ticket; replay-safe) ---
        __threadfence();
        __syncthreads();
        if (tid == 0) {
            int my = atomicAdd(&g_pbar, 1);
            int target = (my / NCTA + 1) * NCTA;
            int cur;
            do {
                asm volatile("ld.global.cg.b32 %0, [%1];" : "=r"(cur) : "l"(&g_pbar));
                if (cur < target) __nanosleep(64);
            } while (cur < target);
        }
        __syncthreads();
    }

    // ===================== PHASE 1: attention (R10) =====================
    const char* gk = (const char*)g_kh + (size_t)b * NN * 8 * 2;
    const char* gv = (const char*)g_vh + (size_t)b * CC * NN * 2;

    ((u32*)sQ)[tid] = ((const u32*)((const char*)g_qh + ((size_t)b * NN + q0) * 16))[tid];

    const u32 skb = svb + 36864;                     // sK base inside uni
    const u32 vA = svb + lane * 144 + 64 * h;
    const u32 vB = vA + 32 * 144;
    const u32 kA = skb + (32 * h + lane) * 16;
    const u32 kDst = skb + tid * 4;
    const u32 vDst = svb + (tid >> 2) * 144 + (tid & 3) * 32;
    const char* kSrc = gk + tid * 4;
    const char* vSrc = gv + ((size_t)(tid >> 2) * NN) * 2 + (tid & 3) * 32;

    // Prologue: stage chunks ck0..ck0+2 into buffers 0..2
#pragma unroll
    for (int p = 0; p < 3; p++) {
        size_t off = (size_t)(ck0 + p) * 64;
        cp4(kDst + p * 1024, kSrc + off * 16);
        cp16(vDst + p * 9216, vSrc + off * 2);
        cp16(vDst + p * 9216 + 16, vSrc + off * 2 + 16);
        cp_commit();
    }

    // sQ written cross-warp: barrier before Q fragment reads.
    __syncthreads();

    const u32 qa0 = *(const u32*)((const char*)sQ + r * 16 + t * 4);
    const u32 qa1 = *(const u32*)((const char*)sQ + (r + 8) * 16 + t * 4);

    float oC[8][4];
#pragma unroll
    for (int i = 0; i < 8; i++)
#pragma unroll
        for (int j = 0; j < 4; j++) oC[i][j] = 0.0f;
    float rs0 = 0.0f, rs1 = 0.0f;

    for (int ck = 0; ck < 32; ck++) {
        const int buf = ck & 3;
        const u32 vOff = buf * 9216;
        const u32 kOff = buf * 1024;

        if (ck < 30) cp_wait2(); else cp_wait0();
        __syncthreads();

        if (ck < 29) {
            size_t off = (size_t)(ck0 + ck + 3) * 64;
            const u32 nb = (ck + 3) & 3;
            cp4(kDst + nb * 1024, kSrc + off * 16);
            cp16(vDst + nb * 9216, vSrc + off * 2);
            cp16(vDst + nb * 9216 + 16, vSrc + off * 2 + 16);
            cp_commit();
        }

        u32 kb[4];
        ldsm_x4(kb[0], kb[1], kb[2], kb[3], kA + kOff);
        float e[4][4];
#pragma unroll
        for (int j = 0; j < 4; j++) {
            e[j][0] = e[j][1] = e[j][2] = e[j][3] = 0.0f;
            mma_bf16_k8(e[j], qa0, qa1, kb[j]);
        }

#pragma unroll
        for (int ks = 0; ks < 2; ks++) {
            u32 bl[4][2], bh[4][2];
            {
                u32 base2 = vOff + 32 * ks;
                ldsm_x4(bl[0][0], bl[1][0], bl[2][0], bl[3][0], vA + base2);
                ldsm_x4(bl[0][1], bl[1][1], bl[2][1], bl[3][1], vA + base2 + 16);
                ldsm_x4(bh[0][0], bh[1][0], bh[2][0], bh[3][0], vB + base2);
                ldsm_x4(bh[0][1], bh[1][1], bh[2][1], bh[3][1], vB + base2 + 16);
            }
            float* e0 = e[2 * ks];
            float* e1 = e[2 * ks + 1];
            float p00 = ex2(e0[0]), p01 = ex2(e0[1]);
            float p02 = ex2(e0[2]), p03 = ex2(e0[3]);
            float p10 = ex2(e1[0]), p11 = ex2(e1[1]);
            float p12 = ex2(e1[2]), p13 = ex2(e1[3]);
            rs0 += p00 + p01 + p10 + p11;
            rs1 += p02 + p03 + p12 + p13;
            u32 a0 = packbf(p00, p01);
            u32 a1 = packbf(p02, p03);
            u32 a2 = packbf(p10, p11);
            u32 a3 = packbf(p12, p13);

#pragma unroll
            for (int cT = 0; cT < 4; cT++)
                mma_bf16_k16(oC[cT], a0, a1, a2, a3, bl[cT][0], bl[cT][1]);
#pragma unroll
            for (int cT = 0; cT < 4; cT++)
                mma_bf16_k16(oC[4 + cT], a0, a1, a2, a3, bh[cT][0], bh[cT][1]);
        }
    }

    // Rowsums
    rs0 += __shfl_xor_sync(0xffffffffu, rs0, 1);
    rs0 += __shfl_xor_sync(0xffffffffu, rs0, 2);
    rs1 += __shfl_xor_sync(0xffffffffu, rs1, 1);
    rs1 += __shfl_xor_sync(0xffffffffu, rs1, 2);
    if (t == 0) {
        sRS[r][h] = rs0;
        sRS[r + 8][h] = rs1;
    }
    __syncthreads();   // sV ring dead; sO may be written

    if (h == 0) {
#pragma unroll
        for (int cT = 0; cT < 8; cT++) {
            int c = 8 * cT + 2 * t;
            sO[r][c] = oC[cT][0];
            sO[r][c + 1] = oC[cT][1];
            sO[r + 8][c] = oC[cT][2];
            sO[r + 8][c + 1] = oC[cT][3];
        }
    }
    __syncthreads();
    if (h == 1) {
#pragma unroll
        for (int cT = 0; cT < 8; cT++) {
            int c = 8 * cT + 2 * t;
            sO[r][c] += oC[cT][0];
            sO[r][c + 1] += oC[cT][1];
            sO[r + 8][c] += oC[cT][2];
            sO[r + 8][c + 1] += oC[cT][3];
        }
    }
    __syncthreads();

    // Partial rowsum + partial bf16 O [s][b][c][n]
    if (tid < 64)
        g_prs[((size_t)s * BB + b) * NN + q0 + tid] = sRS[tid][0] + sRS[tid][1];
    {
        u32* po = (u32*)g_po + ((size_t)s * BB + b) * (CC * NN / 2);
#pragma unroll
        for (int k = 0; k < 8; k++) {
            int i = k * 256 + tid;
            int c = i >> 5, n2 = i & 31;
            po[(size_t)c * (NN / 2) + q0 / 2 + n2] = packbf(sO[2 * n2][c], sO[2 * n2 + 1][c]);
        }
    }

    // Ticket: last CTA of this (tile, b) performs the combine
    __threadfence();
    __syncthreads();
    if (tid == 0) sFlag = ((atomicAdd(&g_tk[b * 64 + blockIdx.x], 1) & (MSPLIT - 1)) == MSPLIT - 1);
    __syncthreads();

    if (sFlag) {
        __threadfence();
        if (tid < 64) {
            float rsum = 0.0f;
#pragma unroll
            for (int ss = 0; ss < MSPLIT; ss++)
                rsum += g_prs[((size_t)ss * BB + b) * NN + q0 + tid];
            sInv[tid] = gammap[0] / rsum;
        }
        __syncthreads();
#pragma unroll
        for (int k = 0; k < 8; k++) {
            int i = k * 256 + tid;
            int c = i >> 5, n2 = i & 31;
            size_t pi = (size_t)c * (NN / 2) + q0 / 2 + n2;
            float vx = 0.0f, vy = 0.0f;
#pragma unroll
            for (int ss = 0; ss < MSPLIT; ss++) {
                float2 v = unpackbf(((const u32*)g_po + ((size_t)ss * BB + b) * (CC * NN / 2))[pi]);
                vx += v.x;
                vy += v.y;
            }
            size_t gi = ((size_t)b * CC + c) * NN + q0 + 2 * n2;
            float2 xv = *(const float2*)&x[gi];
            float2 res;
            res.x = fmaf(vx, sInv[2 * n2], xv.x);
            res.y = fmaf(vy, sInv[2 * n2 + 1], xv.y);
            *(float2*)&out[gi] = res;
        }
    }
}

extern "C" void kernel_launch(void* const* d_in, const int* in_sizes, int n_in,
                              void* d_out, int out_size) {
    const float* x     = (const float*)d_in[0];
    const float* ctx   = (const float*)d_in[1];
    const float* Wq    = (const float*)d_in[2];
    const float* bq    = (const float*)d_in[3];
    const float* Wk    = (const float*)d_in[4];
    const float* bk    = (const float*)d_in[5];
    const float* Wv    = (const float*)d_in[6];
    const float* bv    = (const float*)d_in[7];
    const float* gamma = (const float*)d_in[8];
    float* out = (float*)d_out;

    fused_kernel<<<dim3(64, BB, MSPLIT), 256>>>(x, ctx, Wq, bq, Wk, bk, Wv, bv, gamma, out);
}

// round 17
// speedup vs baseline: 1.3320x; 1.1373x over previous
#include <cuda_runtime.h>
#include <cuda_bf16.h>

#define NN 4096
#define BB 2
#define CC 64
#define NCTA (64 * BB)            // 128 CTAs, 1/SM, all resident

typedef unsigned int u32;

// Scratch
__device__ __nv_bfloat16 g_qh[(size_t)BB * NN * 8];   // [b][n][8c] (q pre-scaled by log2e)
__device__ __nv_bfloat16 g_kh[(size_t)BB * NN * 8];   // [b][m][8c]
__device__ __nv_bfloat16 g_vh[(size_t)BB * CC * NN];  // [b][c][m]
__device__ int g_pbar;                                // grid barrier (monotonic)

// Per-group stage: K 512B (32 m x 16B) + V (64 c-rows x 80B stride, 64B data)
#define STG_K 512
#define STG_SZ 5632
#define GRP_SZ (4 * STG_SZ)       // 4-stage ring
#define DSMEM (4 * GRP_SZ)        // 4 groups = 90112 B

__device__ __forceinline__ u32 packbf(float lo, float hi) {
    u32 r;
    asm("cvt.rn.bf16x2.f32 %0, %1, %2;" : "=r"(r) : "f"(hi), "f"(lo));
    return r;
}
__device__ __forceinline__ float ex2(float x) {
    float y;
    asm("ex2.approx.ftz.f32 %0, %1;" : "=f"(y) : "f"(x));
    return y;
}
__device__ __forceinline__ void mma_bf16_k8(float d[4], u32 a0, u32 a1, u32 b0) {
    asm("mma.sync.aligned.m16n8k8.row.col.f32.bf16.bf16.f32 "
        "{%0,%1,%2,%3}, {%4,%5}, {%6}, {%0,%1,%2,%3};"
        : "+f"(d[0]), "+f"(d[1]), "+f"(d[2]), "+f"(d[3])
        : "r"(a0), "r"(a1), "r"(b0));
}
__device__ __forceinline__ void mma_bf16_k16(float d[4], u32 a0, u32 a1, u32 a2, u32 a3,
                                             u32 b0, u32 b1) {
    asm("mma.sync.aligned.m16n8k16.row.col.f32.bf16.bf16.f32 "
        "{%0,%1,%2,%3}, {%4,%5,%6,%7}, {%8,%9}, {%0,%1,%2,%3};"
        : "+f"(d[0]), "+f"(d[1]), "+f"(d[2]), "+f"(d[3])
        : "r"(a0), "r"(a1), "r"(a2), "r"(a3), "r"(b0), "r"(b1));
}
__device__ __forceinline__ void ldsm_x4(u32& r0, u32& r1, u32& r2, u32& r3, u32 saddr) {
    asm volatile("ldmatrix.sync.aligned.m8n8.x4.shared.b16 {%0,%1,%2,%3}, [%4];"
                 : "=r"(r0), "=r"(r1), "=r"(r2), "=r"(r3) : "r"(saddr));
}
__device__ __forceinline__ void cp16(u32 dst, const void* src) {
    asm volatile("cp.async.cg.shared.global [%0], [%1], 16;" :: "r"(dst), "l"(src));
}
__device__ __forceinline__ void cp4(u32 dst, const void* src) {
    asm volatile("cp.async.ca.shared.global [%0], [%1], 4;" :: "r"(dst), "l"(src));
}
__device__ __forceinline__ void cp_commit() { asm volatile("cp.async.commit_group;"); }
__device__ __forceinline__ void cp_wait0() { asm volatile("cp.async.wait_group 0;"); }
__device__ __forceinline__ void cp_wait2() { asm volatile("cp.async.wait_group 2;"); }
__device__ __forceinline__ void gbar(int id) {
    asm volatile("bar.sync %0, 128;" :: "r"(id) : "memory");
}

// ---------------------------------------------------------------------------
// One 512-thread CTA per (qtile, b): phase 0 proj (64-col tile), grid barrier,
// then full attention over all 64 chunks with 4 warp-groups (qT x h x sh),
// O combined in smem — no partial-O global round trip.
// ---------------------------------------------------------------------------
__global__ __launch_bounds__(512, 1) void fused_kernel(const float* __restrict__ x,
                                                       const float* __restrict__ ctx,
                                                       const float* __restrict__ Wq,
                                                       const float* __restrict__ bq,
                                                       const float* __restrict__ Wk,
                                                       const float* __restrict__ bk,
                                                       const float* __restrict__ Wv,
                                                       const float* __restrict__ bv,
                                                       const float* __restrict__ gammap,
                                                       float* __restrict__ out) {
    extern __shared__ __align__(16) char uni[];        // DSMEM bytes
    __shared__ __nv_bfloat16 sQ[64][8];
    __shared__ float sRS[64][4];
    __shared__ float sInv[64];

    const int tid = threadIdx.x;
    const int b = blockIdx.y;
    const int q0 = blockIdx.x * 64;
    const int lane = tid & 31;
    const int g = lane >> 2;
    const int t = lane & 3;
    const int w = tid >> 5;
    const int qT = w & 3;
    const int gid = w >> 2;          // (h, sh): h = gid&1, sh = gid>>1
    const int h = gid & 1;
    const int sh = gid >> 1;
    const int r = 16 * qT + g;
    const int gt = tid & 127;
    const float LOG2E = 1.4426950408889634f;
    const u32 svb = (u32)__cvta_generic_to_shared(uni);

    // ===================== PHASE 0: projections (64-col tile) ===============
    {
        const int cid = blockIdx.x + 64 * b;           // [0,128)
        const int pb = cid >> 6;
        const int pn0 = (cid & 63) * 64;

        float (*sx)[68] = (float (*)[68])(uni);                 // 17408
        float (*sct)[68] = (float (*)[68])(uni + 17408);        // 17408
        float (*sWv)[68] = (float (*)[68])(uni + 34816);        // 17408 [cc][c]
        float (*sW)[64] = (float (*)[64])(uni + 52224);         // 4096
        float* sb = (float*)(uni + 56320);
        float* sbv = (float*)(uni + 56448);

        // issue ALL staging up front
#pragma unroll
        for (int k = 0; k < 2; k++) {
            int i = k * 512 + tid;
            int row = i >> 4, f4 = (i & 15) * 4;
            u32 so = row * 272 + f4 * 4;
            cp16(svb + so, &x[((size_t)pb * CC + row) * NN + pn0 + f4]);
            cp16(svb + 17408 + so, &ctx[((size_t)pb * CC + row) * NN + pn0 + f4]);
        }
        cp_commit();
#pragma unroll
        for (int k = 0; k < 2; k++) {
            int i4 = k * 512 + tid;
            float4 wv = ((const float4*)Wv)[i4];
            int i = i4 * 4;
            int c = i >> 6, cc = i & 63;
            sWv[cc][c] = wv.x;
            sWv[cc + 1][c] = wv.y;
            sWv[cc + 2][c] = wv.z;
            sWv[cc + 3][c] = wv.w;
        }
        {
            int i = tid;
            if (i < 512) { sW[i >> 6][i & 63] = Wq[i] * LOG2E; }
            int j = tid - 512;
            if (j >= 0 && j < 512) { sW[8 + (j >> 6)][j & 63] = Wk[j]; }
        }
        // both halves must run: 512 threads cover 1024 entries in 2 steps
        {
            int i = 512 + tid;       // second half index for Wq/Wk interleave
            // (handled above for tid<512 only Wq; do Wk for all threads)
        }
        if (tid < 512) {
            // Wk rows for threads 0..511 complete coverage:
            sW[8 + (tid >> 6)][tid & 63] = Wk[tid];
        }
        if (tid < 8) { sb[tid] = bq[tid] * LOG2E; sb[8 + tid] = bk[tid]; }
        if (tid < 64) sbv[tid] = bv[tid];
        cp_wait0();
        __syncthreads();

        // qk compute: 2 rows x 1 col per thread (1024 outputs)
        {
            const int n = tid & 63;
            const int og = tid >> 6;         // 0..7
            const bool isk = og >= 4;
            const int r2 = 2 * (og & 3);
            const int wrow = (isk ? 8 : 0) + r2;
            float a0 = sb[wrow], a1 = sb[wrow + 1];
#pragma unroll
            for (int c = 0; c < 64; c++) {
                float v = isk ? sct[c][n] : sx[c][n];
                a0 = fmaf(sW[wrow][c], v, a0);
                a1 = fmaf(sW[wrow + 1][c], v, a1);
            }
            __nv_bfloat16* dst = isk ? g_kh : g_qh;
            *(u32*)(dst + ((size_t)pb * NN + pn0 + n) * 8 + r2) = packbf(a0, a1);
        }

        // v compute: 4c x 2m per thread (4096 outputs), reuses sct
        {
            const int m2 = (tid & 31) * 2;
            const int cg = (tid >> 5) * 4;
            float acc[4][2];
#pragma unroll
            for (int j = 0; j < 4; j++) acc[j][0] = acc[j][1] = sbv[cg + j];
#pragma unroll
            for (int cc = 0; cc < 64; cc++) {
                float2 vm = *(const float2*)&sct[cc][m2];
                float4 wv = *(const float4*)&sWv[cc][cg];
                float ww[4] = {wv.x, wv.y, wv.z, wv.w};
#pragma unroll
                for (int j = 0; j < 4; j++) {
                    acc[j][0] = fmaf(ww[j], vm.x, acc[j][0]);
                    acc[j][1] = fmaf(ww[j], vm.y, acc[j][1]);
                }
            }
#pragma unroll
            for (int j = 0; j < 4; j++)
                *(u32*)(g_vh + ((size_t)pb * CC + cg + j) * NN + pn0 + m2) = packbf(acc[j][0], acc[j][1]);
        }

        // grid barrier (monotonic epoch; replay-safe)
        __threadfence();
        __syncthreads();
        if (tid == 0) {
            int my = atomicAdd(&g_pbar, 1);
            int target = (my / NCTA + 1) * NCTA;
            int cur;
            do {
                asm volatile("ld.global.cg.b32 %0, [%1];" : "=r"(cur) : "l"(&g_pbar));
                if (cur < target) __nanosleep(64);
            } while (cur < target);
        }
        __syncthreads();
    }

    // ===================== PHASE 1: attention =====================
    const char* gk = (const char*)g_kh + (size_t)b * NN * 8 * 2;
    const char* gv = (const char*)g_vh + (size_t)b * CC * NN * 2;

    ((u32*)sQ)[tid & 511] = ((const u32*)((const char*)g_qh + ((size_t)b * NN + q0) * 16))[tid & 511];

    const u32 rb = svb + gid * GRP_SZ;
    const u32 kA = rb + lane * 16;
    const u32 vA = rb + STG_K + lane * 80;
    const u32 vB = vA + 32 * 80;
    const u32 kDst = rb + gt * 4;
    const u32 vDst = rb + STG_K + (gt >> 1) * 80 + (gt & 1) * 32;
    const char* kSrc = gk + (size_t)(32 * h) * 16 + (gt >> 2) * 16 + (gt & 3) * 4;
    const char* vSrc = gv + ((size_t)(gt >> 1) * NN + 32 * h) * 2 + (gt & 1) * 32;
    const int ck0 = sh * 32;

    // Prologue: stage chunks ck0..ck0+2
#pragma unroll
    for (int p = 0; p < 3; p++) {
        size_t off = (size_t)(ck0 + p) * 64;
        cp4(kDst + p * STG_SZ, kSrc + off * 16);
        cp16(vDst + p * STG_SZ, vSrc + off * 2);
        cp16(vDst + p * STG_SZ + 16, vSrc + off * 2 + 16);
        cp_commit();
    }

    __syncthreads();   // sQ cross-warp

    const u32 qa0 = *(const u32*)((const char*)sQ + r * 16 + t * 4);
    const u32 qa1 = *(const u32*)((const char*)sQ + (r + 8) * 16 + t * 4);

    float oC[8][4];
#pragma unroll
    for (int i = 0; i < 8; i++)
#pragma unroll
        for (int j = 0; j < 4; j++) oC[i][j] = 0.0f;
    float rs0 = 0.0f, rs1 = 0.0f;

    for (int ck = 0; ck < 32; ck++) {
        const u32 stOff = (u32)(ck & 3) * STG_SZ;

        if (ck < 30) cp_wait2(); else cp_wait0();
        gbar(1 + gid);

        if (ck < 29) {
            size_t off = (size_t)(ck0 + ck + 3) * 64;
            const u32 nb = ((ck + 3) & 3) * STG_SZ;
            cp4(kDst + nb, kSrc + off * 16);
            cp16(vDst + nb, vSrc + off * 2);
            cp16(vDst + nb + 16, vSrc + off * 2 + 16);
            cp_commit();
        }

        u32 kb[4];
        ldsm_x4(kb[0], kb[1], kb[2], kb[3], kA + stOff);
        float e[4][4];
#pragma unroll
        for (int j = 0; j < 4; j++) {
            e[j][0] = e[j][1] = e[j][2] = e[j][3] = 0.0f;
            mma_bf16_k8(e[j], qa0, qa1, kb[j]);
        }

#pragma unroll
        for (int ks = 0; ks < 2; ks++) {
            u32 bl[4][2], bh[4][2];
            {
                u32 base = stOff + 32 * ks;
                ldsm_x4(bl[0][0], bl[1][0], bl[2][0], bl[3][0], vA + base);
                ldsm_x4(bl[0][1], bl[1][1], bl[2][1], bl[3][1], vA + base + 16);
                ldsm_x4(bh[0][0], bh[1][0], bh[2][0], bh[3][0], vB + base);
                ldsm_x4(bh[0][1], bh[1][1], bh[2][1], bh[3][1], vB + base + 16);
            }
            float* e0 = e[2 * ks];
            float* e1 = e[2 * ks + 1];
            float p00 = ex2(e0[0]), p01 = ex2(e0[1]);
            float p02 = ex2(e0[2]), p03 = ex2(e0[3]);
            float p10 = ex2(e1[0]), p11 = ex2(e1[1]);
            float p12 = ex2(e1[2]), p13 = ex2(e1[3]);
            rs0 += p00 + p01 + p10 + p11;
            rs1 += p02 + p03 + p12 + p13;
            u32 a0 = packbf(p00, p01);
            u32 a1 = packbf(p02, p03);
            u32 a2 = packbf(p10, p11);
            u32 a3 = packbf(p12, p13);

#pragma unroll
            for (int cT = 0; cT < 4; cT++)
                mma_bf16_k16(oC[cT], a0, a1, a2, a3, bl[cT][0], bl[cT][1]);
#pragma unroll
            for (int cT = 0; cT < 4; cT++)
                mma_bf16_k16(oC[4 + cT], a0, a1, a2, a3, bh[cT][0], bh[cT][1]);
        }
    }

    // Rowsums -> sRS[row][gid]
    rs0 += __shfl_xor_sync(0xffffffffu, rs0, 1);
    rs0 += __shfl_xor_sync(0xffffffffu, rs0, 2);
    rs1 += __shfl_xor_sync(0xffffffffu, rs1, 1);
    rs1 += __shfl_xor_sync(0xffffffffu, rs1, 2);
    if (t == 0) {
        sRS[r][gid] = rs0;
        sRS[r + 8][gid] = rs1;
    }
    __syncthreads();   // all compute done; rings dead

    // Each group writes its O partial to its own smem buffer [64][65] float
    float (*sOg)[65] = (float (*)[65])(uni + gid * 16640);
#pragma unroll
    for (int cT = 0; cT < 8; cT++) {
        int c = 8 * cT + 2 * t;
        sOg[r][c] = oC[cT][0];
        sOg[r][c + 1] = oC[cT][1];
        sOg[r + 8][c] = oC[cT][2];
        sOg[r + 8][c + 1] = oC[cT][3];
    }
    if (tid < 64)
        sInv[tid] = gammap[0] / (sRS[tid][0] + sRS[tid][1] + sRS[tid][2] + sRS[tid][3]);
    __syncthreads();

    // Final: out[b][c][q0+n] = (sum_g sOg[n][c]) * inv[n] + x. 8 c per thread.
    {
        const int n = tid & 63;
        const int cb = tid >> 6;
        float (*sO0)[65] = (float (*)[65])(uni);
        float (*sO1)[65] = (float (*)[65])(uni + 16640);
        float (*sO2)[65] = (float (*)[65])(uni + 33280);
        float (*sO3)[65] = (float (*)[65])(uni + 49920);
        const float inv = sInv[n];
#pragma unroll
        for (int j = 0; j < 8; j++) {
            int c = cb * 8 + j;
            float v = sO0[n][c] + sO1[n][c] + sO2[n][c] + sO3[n][c];
            size_t gi = ((size_t)b * CC + c) * NN + q0 + n;
            out[gi] = fmaf(v, inv, x[gi]);
        }
    }
}

extern "C" void kernel_launch(void* const* d_in, const int* in_sizes, int n_in,
                              void* d_out, int out_size) {
    const float* x     = (const float*)d_in[0];
    const float* ctx   = (const float*)d_in[1];
    const float* Wq    = (const float*)d_in[2];
    const float* bq    = (const float*)d_in[3];
    const float* Wk    = (const float*)d_in[4];
    const float* bk    = (const float*)d_in[5];
    const float* Wv    = (const float*)d_in[6];
    const float* bv    = (const float*)d_in[7];
    const float* gamma = (const float*)d_in[8];
    float* out = (float*)d_out;

    static int configured = 0;
    if (!configured) {
        cudaFuncSetAttribute(fused_kernel, cudaFuncAttributeMaxDynamicSharedMemorySize, DSMEM);
        configured = 1;
    }
    fused_kernel<<<dim3(64, BB), 512, DSMEM>>>(x, ctx, Wq, bq, Wk, bk, Wv, bv, gamma, out);
}